// round 6
// baseline (speedup 1.0000x reference)
#include <cuda_runtime.h>
#include <cuda_bf16.h>
#include <math.h>
#include <stdint.h>

#define BB 2
#define SS 2048
#define DD 1024
#define HH 16
#define HD 64
#define MTOT (BB*SS)   // 4096 rows
#define QKVN 3072      // fused QKV output width

// ---------------------------------------------------------------------------
// Scratch (allocation-free rule: device globals) — all bf16 hi/lo pairs
// ---------------------------------------------------------------------------
__device__ __nv_bfloat16 g_xhi[MTOT*DD], g_xlo[MTOT*DD];
__device__ __nv_bfloat16 g_whi[4*DD*DD], g_wlo[4*DD*DD];
__device__ __nv_bfloat16 g_qkvhi[MTOT*QKVN], g_qkvlo[MTOT*QKVN];
__device__ __nv_bfloat16 g_ahi[MTOT*DD], g_alo[MTOT*DD];

// ---------------------------------------------------------------------------
// PTX helpers (target-agnostic: mma.sync / ldmatrix / cp.async only)
// ---------------------------------------------------------------------------
__device__ __forceinline__ uint32_t smem_u32(const void* p) {
    uint32_t a;
    asm("{ .reg .u64 t; cvta.to.shared.u64 t, %1; cvt.u32.u64 %0, t; }"
        : "=r"(a) : "l"(p));
    return a;
}
#define CP16(s, g) \
    asm volatile("cp.async.cg.shared.global [%0], [%1], 16;" \
                 :: "r"(s), "l"(g) : "memory")
#define CP_COMMIT() asm volatile("cp.async.commit_group;" ::: "memory")
#define CP_WAIT0()  asm volatile("cp.async.wait_group 0;" ::: "memory")
#define LDSM4(r, addr) \
    asm volatile("ldmatrix.sync.aligned.m8n8.x4.shared.b16 {%0,%1,%2,%3}, [%4];" \
                 : "=r"((r)[0]), "=r"((r)[1]), "=r"((r)[2]), "=r"((r)[3]) \
                 : "r"(addr))
#define LDSM4T(r, addr) \
    asm volatile("ldmatrix.sync.aligned.m8n8.x4.trans.shared.b16 {%0,%1,%2,%3}, [%4];" \
                 : "=r"((r)[0]), "=r"((r)[1]), "=r"((r)[2]), "=r"((r)[3]) \
                 : "r"(addr))
#define MMA_BF16(c, a, b0, b1) \
    asm volatile("mma.sync.aligned.m16n8k16.row.col.f32.bf16.bf16.f32 " \
                 "{%0,%1,%2,%3}, {%4,%5,%6,%7}, {%8,%9}, {%0,%1,%2,%3};" \
                 : "+f"((c)[0]), "+f"((c)[1]), "+f"((c)[2]), "+f"((c)[3]) \
                 : "r"((a)[0]), "r"((a)[1]), "r"((a)[2]), "r"((a)[3]), \
                   "r"(b0), "r"(b1))

__device__ __forceinline__ uint32_t pack_bf16(float x, float y) {
    __nv_bfloat162 t = __floats2bfloat162_rn(x, y);
    return *(uint32_t*)&t;
}
__device__ __forceinline__ float fexp2(float x) {
    float y;
    asm("ex2.approx.ftz.f32 %0, %1;" : "=f"(y) : "f"(x));
    return y;
}

// ---------------------------------------------------------------------------
// Split fp32 -> bf16 hi + lo residual
// ---------------------------------------------------------------------------
__device__ __forceinline__ void split4(const float4 v, uint32_t* hi, uint32_t* lo) {
    __nv_bfloat16 h0 = __float2bfloat16_rn(v.x);
    __nv_bfloat16 h1 = __float2bfloat16_rn(v.y);
    __nv_bfloat16 h2 = __float2bfloat16_rn(v.z);
    __nv_bfloat16 h3 = __float2bfloat16_rn(v.w);
    hi[0] = pack_bf16(v.x, v.y);
    hi[1] = pack_bf16(v.z, v.w);
    lo[0] = pack_bf16(v.x - __bfloat162float(h0), v.y - __bfloat162float(h1));
    lo[1] = pack_bf16(v.z - __bfloat162float(h2), v.w - __bfloat162float(h3));
}

__global__ void split_kernel(const float* __restrict__ in,
                             __nv_bfloat16* __restrict__ hi,
                             __nv_bfloat16* __restrict__ lo, int n4) {
    int i = blockIdx.x * blockDim.x + threadIdx.x;
    if (i >= n4) return;
    uint32_t h[2], l[2];
    split4(((const float4*)in)[i], h, l);
    ((uint32_t*)hi)[2*i] = h[0]; ((uint32_t*)hi)[2*i+1] = h[1];
    ((uint32_t*)lo)[2*i] = l[0]; ((uint32_t*)lo)[2*i+1] = l[1];
}

__global__ void wsplit_kernel(const float* __restrict__ w0, const float* __restrict__ w1,
                              const float* __restrict__ w2, const float* __restrict__ w3,
                              __nv_bfloat16* __restrict__ hi,
                              __nv_bfloat16* __restrict__ lo) {
    const int wn4 = DD * DD / 4;
    int idx = blockIdx.x * blockDim.x + threadIdx.x;
    if (idx >= 4 * wn4) return;
    int w = idx / wn4, i = idx - w * wn4;
    const float* src = (w == 0) ? w0 : (w == 1) ? w1 : (w == 2) ? w2 : w3;
    uint32_t h[2], l[2];
    split4(((const float4*)src)[i], h, l);
    ((uint32_t*)hi)[2*idx] = h[0]; ((uint32_t*)hi)[2*idx+1] = h[1];
    ((uint32_t*)lo)[2*idx] = l[0]; ((uint32_t*)lo)[2*idx+1] = l[1];
}

// ---------------------------------------------------------------------------
// HMMA split-precision GEMM (unchanged from R5)
// ---------------------------------------------------------------------------
#define GK 1024
#define RS 40
#define MAT_BYTES (128*RS*2)
#define OFF_AHI 0
#define OFF_ALO (1*MAT_BYTES)
#define OFF_BHI (2*MAT_BYTES)
#define OFF_BLO (3*MAT_BYTES)
#define BUFSTRIDE (4*MAT_BYTES)
#define GEMM_SMEM (2*BUFSTRIDE)   // 81920

__device__ __forceinline__ void issue_chunk(
    const __nv_bfloat16* __restrict__ Ahi, const __nv_bfloat16* __restrict__ Alo,
    const __nv_bfloat16* __restrict__ Bhi, const __nv_bfloat16* __restrict__ Blo,
    int m0, int n0, int kc, uint32_t sbuf, int tid)
{
    #pragma unroll
    for (int t = 0; t < 2; t++) {
        int idx = tid + t * 256;
        int row = idx >> 2;
        int c8  = (idx & 3) * 8;
        size_t ga = (size_t)(m0 + row) * GK + kc + c8;
        size_t gb = (size_t)(n0 + row) * GK + kc + c8;
        uint32_t so = row * (RS * 2) + c8 * 2;
        CP16(sbuf + OFF_AHI + so, Ahi + ga);
        CP16(sbuf + OFF_ALO + so, Alo + ga);
        CP16(sbuf + OFF_BHI + so, Bhi + gb);
        CP16(sbuf + OFF_BLO + so, Blo + gb);
    }
}

template<int OUTMODE>
__global__ __launch_bounds__(256, 2)
void gemm_mma(const __nv_bfloat16* __restrict__ Ahi, const __nv_bfloat16* __restrict__ Alo,
              const __nv_bfloat16* __restrict__ Bhi, const __nv_bfloat16* __restrict__ Blo,
              float* __restrict__ C,
              __nv_bfloat16* __restrict__ Chi, __nv_bfloat16* __restrict__ Clo,
              int ldc)
{
    extern __shared__ char dsm[];
    const uint32_t sb = smem_u32(dsm);

    const int tid  = threadIdx.x;
    const int lane = tid & 31;
    const int wid  = tid >> 5;
    const int wm   = (wid >> 1) * 32;
    const int wn   = (wid & 1) * 64;
    const int m0   = blockIdx.y * 128;
    const int n0   = blockIdx.x * 128;

    const int mrowA = (lane & 7) + 8 * ((lane >> 3) & 1);
    const int khA   = (lane >> 4) & 1;
    const int nrowB = (lane & 7) + 8 * ((lane >> 4) & 1);
    const int khB   = (lane >> 3) & 1;

    float acc[2][8][4];
    #pragma unroll
    for (int mt = 0; mt < 2; mt++)
        #pragma unroll
        for (int nt = 0; nt < 8; nt++)
            #pragma unroll
            for (int i = 0; i < 4; i++) acc[mt][nt][i] = 0.f;

    issue_chunk(Ahi, Alo, Bhi, Blo, m0, n0, 0, sb, tid);
    CP_COMMIT();

    const int NCH = GK / 32;
    for (int c = 0; c < NCH; c++) {
        CP_WAIT0();
        __syncthreads();
        if (c + 1 < NCH) {
            issue_chunk(Ahi, Alo, Bhi, Blo, m0, n0, (c + 1) * 32,
                        sb + ((c + 1) & 1) * BUFSTRIDE, tid);
            CP_COMMIT();
        }
        const uint32_t bu = sb + (c & 1) * BUFSTRIDE;

        #pragma unroll
        for (int ks = 0; ks < 2; ks++) {
            const uint32_t koff = ks * 32;
            uint32_t ah[2][4], al[2][4];
            #pragma unroll
            for (int mt = 0; mt < 2; mt++) {
                uint32_t arow = (wm + mt * 16 + mrowA) * (RS * 2) + khA * 16 + koff;
                LDSM4(ah[mt], bu + OFF_AHI + arow);
                LDSM4(al[mt], bu + OFF_ALO + arow);
            }
            #pragma unroll
            for (int np = 0; np < 4; np++) {
                uint32_t bh[4], bl[4];
                uint32_t brow = (wn + np * 16 + nrowB) * (RS * 2) + khB * 16 + koff;
                LDSM4(bh, bu + OFF_BHI + brow);
                LDSM4(bl, bu + OFF_BLO + brow);
                #pragma unroll
                for (int mt = 0; mt < 2; mt++) {
                    #pragma unroll
                    for (int s = 0; s < 2; s++) {
                        float* cc = acc[mt][np * 2 + s];
                        MMA_BF16(cc, ah[mt], bh[2*s], bh[2*s+1]);
                        MMA_BF16(cc, al[mt], bh[2*s], bh[2*s+1]);
                        MMA_BF16(cc, ah[mt], bl[2*s], bl[2*s+1]);
                    }
                }
            }
        }
        __syncthreads();
    }

    const int r1 = lane >> 2;
    const int cc = (lane & 3) * 2;
    #pragma unroll
    for (int mt = 0; mt < 2; mt++) {
        #pragma unroll
        for (int nt = 0; nt < 8; nt++) {
            size_t base = (size_t)(m0 + wm + mt * 16) * ldc + n0 + wn + nt * 8 + cc;
            if (OUTMODE == 0) {
                *(float2*)&C[base + (size_t)r1 * ldc] =
                    make_float2(acc[mt][nt][0], acc[mt][nt][1]);
                *(float2*)&C[base + (size_t)(r1 + 8) * ldc] =
                    make_float2(acc[mt][nt][2], acc[mt][nt][3]);
            } else {
                #pragma unroll
                for (int r = 0; r < 2; r++) {
                    float p0 = acc[mt][nt][2*r], p1 = acc[mt][nt][2*r+1];
                    __nv_bfloat16 h0 = __float2bfloat16_rn(p0);
                    __nv_bfloat16 h1 = __float2bfloat16_rn(p1);
                    size_t a = base + (size_t)(r1 + 8*r) * ldc;
                    *(uint32_t*)&Chi[a] = pack_bf16(p0, p1);
                    *(uint32_t*)&Clo[a] = pack_bf16(p0 - __bfloat162float(h0),
                                                    p1 - __bfloat162float(h1));
                }
            }
        }
    }
}

// ---------------------------------------------------------------------------
// Tensor-core flash attention — low-register version for 2 CTAs/SM.
// Q kept in smem (ldmatrix per tile); P packed per-t-group inside PV loop;
// softmax in exp2 domain.
// ---------------------------------------------------------------------------
#define KSTR 144
#define TILE_B (64*KSTR)
#define AT_KV   36864
#define AT_BUF  (4*TILE_B)
#define ATT_SMEM (AT_KV + 2*AT_BUF)   // 110592
#define SM_SCALE 0.18033688011112042f  // 0.125 * log2(e)

__global__ __launch_bounds__(256, 2)
void attn_mma(const __nv_bfloat16* __restrict__ qkvhi,
              const __nv_bfloat16* __restrict__ qkvlo,
              __nv_bfloat16* __restrict__ ohi, __nv_bfloat16* __restrict__ olo)
{
    extern __shared__ char dsm[];
    const uint32_t sQ  = smem_u32(dsm);
    const uint32_t sKV = sQ + AT_KV;

    const int tid  = threadIdx.x;
    const int lane = tid & 31;
    const int wid  = tid >> 5;
    const int qt   = gridDim.x - 1 - blockIdx.x;
    const int bh   = blockIdx.y;
    const int b    = bh >> 4;
    const int h    = bh & 15;
    const int q0   = qt * 128;

    const size_t rowbase = (size_t)b * SS * QKVN + h * HD;
    const __nv_bfloat16* qhi = qkvhi + rowbase;
    const __nv_bfloat16* qlo = qkvlo + rowbase;
    const __nv_bfloat16* khi = qkvhi + rowbase + DD;
    const __nv_bfloat16* klo = qkvlo + rowbase + DD;
    const __nv_bfloat16* vhi = qkvhi + rowbase + 2 * DD;
    const __nv_bfloat16* vlo = qkvlo + rowbase + 2 * DD;

    // ---- stage Q (hi/lo) + first K/V tile in ONE async group ----
    #pragma unroll
    for (int i = 0; i < 8; i++) {
        int idx = tid + i * 256;
        int v   = idx & 1023;
        int row = v >> 3;
        int c8  = (v & 7) * 8;
        const __nv_bfloat16* src = (i < 4) ? qhi : qlo;
        CP16(sQ + (i < 4 ? 0 : 128*KSTR) + row * KSTR + c8 * 2,
             src + (size_t)(q0 + row) * QKVN + c8);
    }
    #pragma unroll
    for (int i = 0; i < 8; i++) {
        int idx = tid + i * 256;
        int v   = idx & 511;
        int row = v >> 3;
        int c8  = (v & 7) * 8;
        int arr = i >> 1;
        const __nv_bfloat16* src = (arr == 0) ? khi : (arr == 1) ? klo
                                 : (arr == 2) ? vhi : vlo;
        CP16(sKV + arr * TILE_B + row * KSTR + c8 * 2,
             src + (size_t)row * QKVN + c8);
    }
    CP_COMMIT();

    const int wq    = wid * 16;
    const int mrowA = (lane & 7) + 8 * ((lane >> 3) & 1);
    const int khA   = (lane >> 4) & 1;
    const int nrowB = (lane & 7) + 8 * ((lane >> 4) & 1);
    const int khB   = (lane >> 3) & 1;
    const int vrow  = (lane & 7) + 8 * ((lane >> 3) & 1);
    const int vcol8 = ((lane >> 4) & 1) * 8;
    const int r1    = lane >> 2;
    const int c2    = (lane & 3) * 2;

    float oacc[8][4];
    #pragma unroll
    for (int n = 0; n < 8; n++)
        #pragma unroll
        for (int i = 0; i < 4; i++) oacc[n][i] = 0.f;
    float mrow[2] = {-INFINITY, -INFINITY};   // log2 domain
    float lrow[2] = {0.f, 0.f};

    const int ntiles = 2 * qt + 2;
    for (int kt = 0; kt < ntiles; kt++) {
        CP_WAIT0();
        __syncthreads();
        if (kt + 1 < ntiles) {
            uint32_t nbuf = sKV + ((kt + 1) & 1) * AT_BUF;
            #pragma unroll
            for (int i = 0; i < 8; i++) {
                int idx = tid + i * 256;
                int v   = idx & 511;
                int row = v >> 3;
                int c8  = (v & 7) * 8;
                int arr = i >> 1;
                const __nv_bfloat16* src = (arr == 0) ? khi : (arr == 1) ? klo
                                         : (arr == 2) ? vhi : vlo;
                CP16(nbuf + arr * TILE_B + row * KSTR + c8 * 2,
                     src + (size_t)((kt + 1) * 64 + row) * QKVN + c8);
            }
            CP_COMMIT();
        }
        const uint32_t bu = sKV + (kt & 1) * AT_BUF;

        // ---- S = Q K^T (3-term split); Q re-read from smem each t ----
        float s[8][4];
        #pragma unroll
        for (int j = 0; j < 8; j++)
            #pragma unroll
            for (int i = 0; i < 4; i++) s[j][i] = 0.f;

        #pragma unroll
        for (int t = 0; t < 4; t++) {
            uint32_t qh[4], ql[4];
            uint32_t qa = sQ + (wq + mrowA) * KSTR + khA * 16 + t * 32;
            LDSM4(qh, qa);
            LDSM4(ql, qa + 128*KSTR);
            #pragma unroll
            for (int j2 = 0; j2 < 4; j2++) {
                uint32_t kh[4], kl[4];
                uint32_t brow = (j2 * 16 + nrowB) * KSTR + khB * 16 + t * 32;
                LDSM4(kh, bu + brow);
                LDSM4(kl, bu + TILE_B + brow);
                #pragma unroll
                for (int s2 = 0; s2 < 2; s2++) {
                    float* cc = s[j2 * 2 + s2];
                    MMA_BF16(cc, qh, kh[2*s2], kh[2*s2+1]);
                    MMA_BF16(cc, ql, kh[2*s2], kh[2*s2+1]);
                    MMA_BF16(cc, qh, kl[2*s2], kl[2*s2+1]);
                }
            }
        }

        // ---- scale (exp2 domain) + causal mask ----
        const bool masked = (kt >= ntiles - 2);
        #pragma unroll
        for (int j = 0; j < 8; j++) {
            #pragma unroll
            for (int i = 0; i < 4; i++) {
                float sv = s[j][i] * SM_SCALE;
                if (masked) {
                    int qrow = q0 + wq + r1 + ((i >> 1) << 3);
                    int key  = kt * 64 + j * 8 + c2 + (i & 1);
                    if (key > qrow) sv = -INFINITY;
                }
                s[j][i] = sv;
            }
        }

        // ---- online softmax (exp2 domain) ----
        #pragma unroll
        for (int r = 0; r < 2; r++) {
            float mx = -INFINITY;
            #pragma unroll
            for (int j = 0; j < 8; j++)
                mx = fmaxf(mx, fmaxf(s[j][2*r], s[j][2*r+1]));
            mx = fmaxf(mx, __shfl_xor_sync(0xffffffffu, mx, 1));
            mx = fmaxf(mx, __shfl_xor_sync(0xffffffffu, mx, 2));
            float mnew  = fmaxf(mrow[r], mx);
            float alpha = fexp2(mrow[r] - mnew);
            float psum = 0.f;
            #pragma unroll
            for (int j = 0; j < 8; j++) {
                float p0 = fexp2(s[j][2*r]   - mnew);
                float p1 = fexp2(s[j][2*r+1] - mnew);
                s[j][2*r] = p0; s[j][2*r+1] = p1;
                psum += p0 + p1;
            }
            psum += __shfl_xor_sync(0xffffffffu, psum, 1);
            psum += __shfl_xor_sync(0xffffffffu, psum, 2);
            lrow[r] = lrow[r] * alpha + psum;
            mrow[r] = mnew;
            #pragma unroll
            for (int n = 0; n < 8; n++) {
                oacc[n][2*r]   *= alpha;
                oacc[n][2*r+1] *= alpha;
            }
        }

        // ---- O += P V: pack P per t-group, MMA immediately ----
        #pragma unroll
        for (int t = 0; t < 4; t++) {
            uint32_t ph[4], pl[4];
            #pragma unroll
            for (int half = 0; half < 2; half++) {
                int j = 2 * t + half;
                #pragma unroll
                for (int r = 0; r < 2; r++) {
                    float p0 = s[j][2*r], p1 = s[j][2*r+1];
                    __nv_bfloat16 h0 = __float2bfloat16_rn(p0);
                    __nv_bfloat16 h1 = __float2bfloat16_rn(p1);
                    ph[half*2 + r] = pack_bf16(p0, p1);
                    pl[half*2 + r] = pack_bf16(p0 - __bfloat162float(h0),
                                               p1 - __bfloat162float(h1));
                }
            }
            #pragma unroll
            for (int n2 = 0; n2 < 4; n2++) {
                uint32_t vh[4], vl[4];
                uint32_t va = (t * 16 + vrow) * KSTR + (n2 * 16 + vcol8) * 2;
                LDSM4T(vh, bu + 2 * TILE_B + va);
                LDSM4T(vl, bu + 3 * TILE_B + va);
                #pragma unroll
                for (int s2 = 0; s2 < 2; s2++) {
                    float* cc = oacc[n2 * 2 + s2];
                    MMA_BF16(cc, ph, vh[2*s2], vh[2*s2+1]);
                    MMA_BF16(cc, pl, vh[2*s2], vh[2*s2+1]);
                    MMA_BF16(cc, ph, vl[2*s2], vl[2*s2+1]);
                }
            }
        }
    }

    // ---- epilogue: normalize, write bf16 hi/lo ----
    #pragma unroll
    for (int r = 0; r < 2; r++) {
        float linv = 1.f / lrow[r];
        int qrow = q0 + wq + r1 + 8 * r;
        size_t base = (size_t)(b * SS + qrow) * DD + h * HD + c2;
        #pragma unroll
        for (int n = 0; n < 8; n++) {
            float p0 = oacc[n][2*r] * linv;
            float p1 = oacc[n][2*r+1] * linv;
            __nv_bfloat16 h0 = __float2bfloat16_rn(p0);
            __nv_bfloat16 h1 = __float2bfloat16_rn(p1);
            *(uint32_t*)&ohi[base + n * 8] = pack_bf16(p0, p1);
            *(uint32_t*)&olo[base + n * 8] = pack_bf16(p0 - __bfloat162float(h0),
                                                       p1 - __bfloat162float(h1));
        }
    }
}

// ---------------------------------------------------------------------------
extern "C" void kernel_launch(void* const* d_in, const int* in_sizes, int n_in,
                              void* d_out, int out_size) {
    const float* x  = (const float*)d_in[0];
    const float* Wq = (const float*)d_in[1];
    const float* Wk = (const float*)d_in[2];
    const float* Wv = (const float*)d_in[3];
    const float* Wo = (const float*)d_in[4];
    float* out = (float*)d_out;

    void *p_xhi, *p_xlo, *p_whi, *p_wlo, *p_qkvhi, *p_qkvlo, *p_ahi, *p_alo;
    cudaGetSymbolAddress(&p_xhi, g_xhi);
    cudaGetSymbolAddress(&p_xlo, g_xlo);
    cudaGetSymbolAddress(&p_whi, g_whi);
    cudaGetSymbolAddress(&p_wlo, g_wlo);
    cudaGetSymbolAddress(&p_qkvhi, g_qkvhi);
    cudaGetSymbolAddress(&p_qkvlo, g_qkvlo);
    cudaGetSymbolAddress(&p_ahi, g_ahi);
    cudaGetSymbolAddress(&p_alo, g_alo);

    __nv_bfloat16* xhi = (__nv_bfloat16*)p_xhi;
    __nv_bfloat16* xlo = (__nv_bfloat16*)p_xlo;
    __nv_bfloat16* whi = (__nv_bfloat16*)p_whi;
    __nv_bfloat16* wlo = (__nv_bfloat16*)p_wlo;
    __nv_bfloat16* qkvhi = (__nv_bfloat16*)p_qkvhi;
    __nv_bfloat16* qkvlo = (__nv_bfloat16*)p_qkvlo;
    __nv_bfloat16* ahi = (__nv_bfloat16*)p_ahi;
    __nv_bfloat16* alo = (__nv_bfloat16*)p_alo;

    const int xn4 = MTOT * DD / 4;
    const int wtot4 = 4 * DD * DD / 4;
    split_kernel<<<xn4 / 256, 256>>>(x, xhi, xlo, xn4);
    wsplit_kernel<<<(wtot4 + 255) / 256, 256>>>(Wq, Wk, Wv, Wo, whi, wlo);

    cudaFuncSetAttribute(gemm_mma<0>,
                         cudaFuncAttributeMaxDynamicSharedMemorySize, GEMM_SMEM);
    cudaFuncSetAttribute(gemm_mma<1>,
                         cudaFuncAttributeMaxDynamicSharedMemorySize, GEMM_SMEM);

    gemm_mma<1><<<dim3(QKVN / 128, MTOT / 128), 256, GEMM_SMEM>>>(
        xhi, xlo, whi, wlo, nullptr, qkvhi, qkvlo, QKVN);

    cudaFuncSetAttribute(attn_mma,
                         cudaFuncAttributeMaxDynamicSharedMemorySize, ATT_SMEM);
    attn_mma<<<dim3(SS / 128, BB * HH), 256, ATT_SMEM>>>(qkvhi, qkvlo, ahi, alo);

    gemm_mma<0><<<dim3(DD / 128, MTOT / 128), 256, GEMM_SMEM>>>(
        ahi, alo, whi + 3*DD*DD, wlo + 3*DD*DD, out, nullptr, nullptr, DD);
}

// round 7
// speedup vs baseline: 1.0190x; 1.0190x over previous
#include <cuda_runtime.h>
#include <cuda_bf16.h>
#include <math.h>
#include <stdint.h>

#define BB 2
#define SS 2048
#define DD 1024
#define HH 16
#define HD 64
#define MTOT (BB*SS)   // 4096 rows
#define QKVN 3072      // fused QKV output width

// ---------------------------------------------------------------------------
// Scratch (allocation-free rule: device globals) — all bf16 hi/lo pairs
// ---------------------------------------------------------------------------
__device__ __nv_bfloat16 g_xhi[MTOT*DD], g_xlo[MTOT*DD];
__device__ __nv_bfloat16 g_whi[4*DD*DD], g_wlo[4*DD*DD];
__device__ __nv_bfloat16 g_qkvhi[MTOT*QKVN], g_qkvlo[MTOT*QKVN];
__device__ __nv_bfloat16 g_ahi[MTOT*DD], g_alo[MTOT*DD];

// ---------------------------------------------------------------------------
// PTX helpers (target-agnostic: mma.sync / ldmatrix / cp.async only)
// ---------------------------------------------------------------------------
__device__ __forceinline__ uint32_t smem_u32(const void* p) {
    uint32_t a;
    asm("{ .reg .u64 t; cvta.to.shared.u64 t, %1; cvt.u32.u64 %0, t; }"
        : "=r"(a) : "l"(p));
    return a;
}
#define CP16(s, g) \
    asm volatile("cp.async.cg.shared.global [%0], [%1], 16;" \
                 :: "r"(s), "l"(g) : "memory")
#define CP_COMMIT() asm volatile("cp.async.commit_group;" ::: "memory")
#define CP_WAIT0()  asm volatile("cp.async.wait_group 0;" ::: "memory")
#define LDSM4(r, addr) \
    asm volatile("ldmatrix.sync.aligned.m8n8.x4.shared.b16 {%0,%1,%2,%3}, [%4];" \
                 : "=r"((r)[0]), "=r"((r)[1]), "=r"((r)[2]), "=r"((r)[3]) \
                 : "r"(addr))
#define LDSM4T(r, addr) \
    asm volatile("ldmatrix.sync.aligned.m8n8.x4.trans.shared.b16 {%0,%1,%2,%3}, [%4];" \
                 : "=r"((r)[0]), "=r"((r)[1]), "=r"((r)[2]), "=r"((r)[3]) \
                 : "r"(addr))
#define MMA_BF16(c, a, b0, b1) \
    asm volatile("mma.sync.aligned.m16n8k16.row.col.f32.bf16.bf16.f32 " \
                 "{%0,%1,%2,%3}, {%4,%5,%6,%7}, {%8,%9}, {%0,%1,%2,%3};" \
                 : "+f"((c)[0]), "+f"((c)[1]), "+f"((c)[2]), "+f"((c)[3]) \
                 : "r"((a)[0]), "r"((a)[1]), "r"((a)[2]), "r"((a)[3]), \
                   "r"(b0), "r"(b1))

__device__ __forceinline__ uint32_t pack_bf16(float x, float y) {
    __nv_bfloat162 t = __floats2bfloat162_rn(x, y);
    return *(uint32_t*)&t;
}
__device__ __forceinline__ float fexp2(float x) {
    float y;
    asm("ex2.approx.ftz.f32 %0, %1;" : "=f"(y) : "f"(x));
    return y;
}

// ---------------------------------------------------------------------------
// Split fp32 -> bf16 hi + lo residual
// ---------------------------------------------------------------------------
__device__ __forceinline__ void split4(const float4 v, uint32_t* hi, uint32_t* lo) {
    __nv_bfloat16 h0 = __float2bfloat16_rn(v.x);
    __nv_bfloat16 h1 = __float2bfloat16_rn(v.y);
    __nv_bfloat16 h2 = __float2bfloat16_rn(v.z);
    __nv_bfloat16 h3 = __float2bfloat16_rn(v.w);
    hi[0] = pack_bf16(v.x, v.y);
    hi[1] = pack_bf16(v.z, v.w);
    lo[0] = pack_bf16(v.x - __bfloat162float(h0), v.y - __bfloat162float(h1));
    lo[1] = pack_bf16(v.z - __bfloat162float(h2), v.w - __bfloat162float(h3));
}

__global__ void split_kernel(const float* __restrict__ in,
                             __nv_bfloat16* __restrict__ hi,
                             __nv_bfloat16* __restrict__ lo, int n4) {
    int i = blockIdx.x * blockDim.x + threadIdx.x;
    if (i >= n4) return;
    uint32_t h[2], l[2];
    split4(((const float4*)in)[i], h, l);
    ((uint32_t*)hi)[2*i] = h[0]; ((uint32_t*)hi)[2*i+1] = h[1];
    ((uint32_t*)lo)[2*i] = l[0]; ((uint32_t*)lo)[2*i+1] = l[1];
}

__global__ void wsplit_kernel(const float* __restrict__ w0, const float* __restrict__ w1,
                              const float* __restrict__ w2, const float* __restrict__ w3,
                              __nv_bfloat16* __restrict__ hi,
                              __nv_bfloat16* __restrict__ lo) {
    const int wn4 = DD * DD / 4;
    int idx = blockIdx.x * blockDim.x + threadIdx.x;
    if (idx >= 4 * wn4) return;
    int w = idx / wn4, i = idx - w * wn4;
    const float* src = (w == 0) ? w0 : (w == 1) ? w1 : (w == 2) ? w2 : w3;
    uint32_t h[2], l[2];
    split4(((const float4*)src)[i], h, l);
    ((uint32_t*)hi)[2*idx] = h[0]; ((uint32_t*)hi)[2*idx+1] = h[1];
    ((uint32_t*)lo)[2*idx] = l[0]; ((uint32_t*)lo)[2*idx+1] = l[1];
}

// ---------------------------------------------------------------------------
// Persistent HMMA split-precision GEMM: C[*, *] = A * B^T, tiles strided
// across a fixed CTA grid (no wave-quantization loss).
// ---------------------------------------------------------------------------
#define GK 1024
#define RS 40
#define MAT_BYTES (128*RS*2)
#define OFF_AHI 0
#define OFF_ALO (1*MAT_BYTES)
#define OFF_BHI (2*MAT_BYTES)
#define OFF_BLO (3*MAT_BYTES)
#define BUFSTRIDE (4*MAT_BYTES)
#define GEMM_SMEM (2*BUFSTRIDE)   // 81920

__device__ __forceinline__ void issue_chunk(
    const __nv_bfloat16* __restrict__ Ahi, const __nv_bfloat16* __restrict__ Alo,
    const __nv_bfloat16* __restrict__ Bhi, const __nv_bfloat16* __restrict__ Blo,
    int m0, int n0, int kc, uint32_t sbuf, int tid)
{
    #pragma unroll
    for (int t = 0; t < 2; t++) {
        int idx = tid + t * 256;
        int row = idx >> 2;
        int c8  = (idx & 3) * 8;
        size_t ga = (size_t)(m0 + row) * GK + kc + c8;
        size_t gb = (size_t)(n0 + row) * GK + kc + c8;
        uint32_t so = row * (RS * 2) + c8 * 2;
        CP16(sbuf + OFF_AHI + so, Ahi + ga);
        CP16(sbuf + OFF_ALO + so, Alo + ga);
        CP16(sbuf + OFF_BHI + so, Bhi + gb);
        CP16(sbuf + OFF_BLO + so, Blo + gb);
    }
}

template<int OUTMODE>
__global__ __launch_bounds__(256, 2)
void gemm_mma(const __nv_bfloat16* __restrict__ Ahi, const __nv_bfloat16* __restrict__ Alo,
              const __nv_bfloat16* __restrict__ Bhi, const __nv_bfloat16* __restrict__ Blo,
              float* __restrict__ C,
              __nv_bfloat16* __restrict__ Chi, __nv_bfloat16* __restrict__ Clo,
              int ldc, int ntx, int ntiles)
{
    extern __shared__ char dsm[];
    const uint32_t sb = smem_u32(dsm);

    const int tid  = threadIdx.x;
    const int lane = tid & 31;
    const int wid  = tid >> 5;
    const int wm   = (wid >> 1) * 32;
    const int wn   = (wid & 1) * 64;

    const int mrowA = (lane & 7) + 8 * ((lane >> 3) & 1);
    const int khA   = (lane >> 4) & 1;
    const int nrowB = (lane & 7) + 8 * ((lane >> 4) & 1);
    const int khB   = (lane >> 3) & 1;
    const int r1 = lane >> 2;
    const int cc = (lane & 3) * 2;

    for (int tile = blockIdx.x; tile < ntiles; tile += gridDim.x) {
        const int m0 = (tile / ntx) * 128;
        const int n0 = (tile % ntx) * 128;

        float acc[2][8][4];
        #pragma unroll
        for (int mt = 0; mt < 2; mt++)
            #pragma unroll
            for (int nt = 0; nt < 8; nt++)
                #pragma unroll
                for (int i = 0; i < 4; i++) acc[mt][nt][i] = 0.f;

        issue_chunk(Ahi, Alo, Bhi, Blo, m0, n0, 0, sb, tid);
        CP_COMMIT();

        const int NCH = GK / 32;
        for (int c = 0; c < NCH; c++) {
            CP_WAIT0();
            __syncthreads();
            if (c + 1 < NCH) {
                issue_chunk(Ahi, Alo, Bhi, Blo, m0, n0, (c + 1) * 32,
                            sb + ((c + 1) & 1) * BUFSTRIDE, tid);
                CP_COMMIT();
            }
            const uint32_t bu = sb + (c & 1) * BUFSTRIDE;

            #pragma unroll
            for (int ks = 0; ks < 2; ks++) {
                const uint32_t koff = ks * 32;
                uint32_t ah[2][4], al[2][4];
                #pragma unroll
                for (int mt = 0; mt < 2; mt++) {
                    uint32_t arow = (wm + mt * 16 + mrowA) * (RS * 2) + khA * 16 + koff;
                    LDSM4(ah[mt], bu + OFF_AHI + arow);
                    LDSM4(al[mt], bu + OFF_ALO + arow);
                }
                #pragma unroll
                for (int np = 0; np < 4; np++) {
                    uint32_t bh[4], bl[4];
                    uint32_t brow = (wn + np * 16 + nrowB) * (RS * 2) + khB * 16 + koff;
                    LDSM4(bh, bu + OFF_BHI + brow);
                    LDSM4(bl, bu + OFF_BLO + brow);
                    #pragma unroll
                    for (int mt = 0; mt < 2; mt++) {
                        #pragma unroll
                        for (int s = 0; s < 2; s++) {
                            float* cv = acc[mt][np * 2 + s];
                            MMA_BF16(cv, ah[mt], bh[2*s], bh[2*s+1]);
                            MMA_BF16(cv, al[mt], bh[2*s], bh[2*s+1]);
                            MMA_BF16(cv, ah[mt], bl[2*s], bl[2*s+1]);
                        }
                    }
                }
            }
            __syncthreads();
        }

        #pragma unroll
        for (int mt = 0; mt < 2; mt++) {
            #pragma unroll
            for (int nt = 0; nt < 8; nt++) {
                size_t base = (size_t)(m0 + wm + mt * 16) * ldc + n0 + wn + nt * 8 + cc;
                if (OUTMODE == 0) {
                    *(float2*)&C[base + (size_t)r1 * ldc] =
                        make_float2(acc[mt][nt][0], acc[mt][nt][1]);
                    *(float2*)&C[base + (size_t)(r1 + 8) * ldc] =
                        make_float2(acc[mt][nt][2], acc[mt][nt][3]);
                } else {
                    #pragma unroll
                    for (int r = 0; r < 2; r++) {
                        float p0 = acc[mt][nt][2*r], p1 = acc[mt][nt][2*r+1];
                        __nv_bfloat16 h0 = __float2bfloat16_rn(p0);
                        __nv_bfloat16 h1 = __float2bfloat16_rn(p1);
                        size_t a = base + (size_t)(r1 + 8*r) * ldc;
                        *(uint32_t*)&Chi[a] = pack_bf16(p0, p1);
                        *(uint32_t*)&Clo[a] = pack_bf16(p0 - __bfloat162float(h0),
                                                        p1 - __bfloat162float(h1));
                    }
                }
            }
        }
    }
}

// ---------------------------------------------------------------------------
// Tensor-core flash attention — 64-row Q tiles, 128-thread CTAs (4 warps).
// Halves the longest serial CTA; 1024 CTAs pack the causal triangle tightly.
// ---------------------------------------------------------------------------
#define KSTR 144
#define TILE_B (64*KSTR)          // 9216
#define AT_Q    (2*64*KSTR)       // 18432 (Q hi + lo, 64 rows)
#define AT_BUF  (4*TILE_B)        // 36864
#define ATT_SMEM (AT_Q + 2*AT_BUF)   // 92160
#define SM_SCALE 0.18033688011112042f  // 0.125 * log2(e)

__global__ __launch_bounds__(128, 2)
void attn_mma(const __nv_bfloat16* __restrict__ qkvhi,
              const __nv_bfloat16* __restrict__ qkvlo,
              __nv_bfloat16* __restrict__ ohi, __nv_bfloat16* __restrict__ olo)
{
    extern __shared__ char dsm[];
    const uint32_t sQ  = smem_u32(dsm);
    const uint32_t sKV = sQ + AT_Q;

    const int tid  = threadIdx.x;
    const int lane = tid & 31;
    const int wid  = tid >> 5;            // 0..3
    const int qt   = gridDim.x - 1 - blockIdx.x;   // 0..31, long first
    const int bh   = blockIdx.y;
    const int b    = bh >> 4;
    const int h    = bh & 15;
    const int q0   = qt * 64;

    const size_t rowbase = (size_t)b * SS * QKVN + h * HD;
    const __nv_bfloat16* qhi = qkvhi + rowbase;
    const __nv_bfloat16* qlo = qkvlo + rowbase;
    const __nv_bfloat16* khi = qkvhi + rowbase + DD;
    const __nv_bfloat16* klo = qkvlo + rowbase + DD;
    const __nv_bfloat16* vhi = qkvhi + rowbase + 2 * DD;
    const __nv_bfloat16* vlo = qkvlo + rowbase + 2 * DD;

    // ---- stage Q (hi/lo, 64 rows) + first K/V tile in ONE async group ----
    #pragma unroll
    for (int i = 0; i < 8; i++) {          // 1024 CP16: Q hi (512) + Q lo (512)
        int idx = tid + i * 128;
        int v   = idx & 511;
        int row = v >> 3;
        int c8  = (v & 7) * 8;
        const __nv_bfloat16* src = (idx < 512) ? qhi : qlo;
        CP16(sQ + (idx < 512 ? 0 : 64*KSTR) + row * KSTR + c8 * 2,
             src + (size_t)(q0 + row) * QKVN + c8);
    }
    #pragma unroll
    for (int i = 0; i < 16; i++) {         // 2048 CP16: Khi,Klo,Vhi,Vlo
        int idx = tid + i * 128;
        int v   = idx & 511;
        int row = v >> 3;
        int c8  = (v & 7) * 8;
        int arr = idx >> 9;
        const __nv_bfloat16* src = (arr == 0) ? khi : (arr == 1) ? klo
                                 : (arr == 2) ? vhi : vlo;
        CP16(sKV + arr * TILE_B + row * KSTR + c8 * 2,
             src + (size_t)row * QKVN + c8);
    }
    CP_COMMIT();

    const int wq    = wid * 16;
    const int mrowA = (lane & 7) + 8 * ((lane >> 3) & 1);
    const int khA   = (lane >> 4) & 1;
    const int nrowB = (lane & 7) + 8 * ((lane >> 4) & 1);
    const int khB   = (lane >> 3) & 1;
    const int vrow  = (lane & 7) + 8 * ((lane >> 3) & 1);
    const int vcol8 = ((lane >> 4) & 1) * 8;
    const int r1    = lane >> 2;
    const int c2    = (lane & 3) * 2;

    float oacc[8][4];
    #pragma unroll
    for (int n = 0; n < 8; n++)
        #pragma unroll
        for (int i = 0; i < 4; i++) oacc[n][i] = 0.f;
    float mrow[2] = {-INFINITY, -INFINITY};   // log2 domain
    float lrow[2] = {0.f, 0.f};

    const int ntiles = qt + 1;
    for (int kt = 0; kt < ntiles; kt++) {
        CP_WAIT0();
        __syncthreads();
        if (kt + 1 < ntiles) {
            uint32_t nbuf = sKV + ((kt + 1) & 1) * AT_BUF;
            #pragma unroll
            for (int i = 0; i < 16; i++) {
                int idx = tid + i * 128;
                int v   = idx & 511;
                int row = v >> 3;
                int c8  = (v & 7) * 8;
                int arr = idx >> 9;
                const __nv_bfloat16* src = (arr == 0) ? khi : (arr == 1) ? klo
                                         : (arr == 2) ? vhi : vlo;
                CP16(nbuf + arr * TILE_B + row * KSTR + c8 * 2,
                     src + (size_t)((kt + 1) * 64 + row) * QKVN + c8);
            }
            CP_COMMIT();
        }
        const uint32_t bu = sKV + (kt & 1) * AT_BUF;

        // ---- S = Q K^T (3-term split) ----
        float s[8][4];
        #pragma unroll
        for (int j = 0; j < 8; j++)
            #pragma unroll
            for (int i = 0; i < 4; i++) s[j][i] = 0.f;

        #pragma unroll
        for (int t = 0; t < 4; t++) {
            uint32_t qh[4], ql[4];
            uint32_t qa = sQ + (wq + mrowA) * KSTR + khA * 16 + t * 32;
            LDSM4(qh, qa);
            LDSM4(ql, qa + 64*KSTR);
            #pragma unroll
            for (int j2 = 0; j2 < 4; j2++) {
                uint32_t kh[4], kl[4];
                uint32_t brow = (j2 * 16 + nrowB) * KSTR + khB * 16 + t * 32;
                LDSM4(kh, bu + brow);
                LDSM4(kl, bu + TILE_B + brow);
                #pragma unroll
                for (int s2 = 0; s2 < 2; s2++) {
                    float* cv = s[j2 * 2 + s2];
                    MMA_BF16(cv, qh, kh[2*s2], kh[2*s2+1]);
                    MMA_BF16(cv, ql, kh[2*s2], kh[2*s2+1]);
                    MMA_BF16(cv, qh, kl[2*s2], kl[2*s2+1]);
                }
            }
        }

        // ---- scale (exp2 domain) + causal mask (diagonal tile only) ----
        const bool masked = (kt == ntiles - 1);
        #pragma unroll
        for (int j = 0; j < 8; j++) {
            #pragma unroll
            for (int i = 0; i < 4; i++) {
                float sv = s[j][i] * SM_SCALE;
                if (masked) {
                    int qrow = wq + r1 + ((i >> 1) << 3);        // within tile
                    int key  = (kt - qt) * 64 + j * 8 + c2 + (i & 1);
                    if (key > qrow) sv = -INFINITY;
                }
                s[j][i] = sv;
            }
        }

        // ---- online softmax (exp2 domain) ----
        #pragma unroll
        for (int r = 0; r < 2; r++) {
            float mx = -INFINITY;
            #pragma unroll
            for (int j = 0; j < 8; j++)
                mx = fmaxf(mx, fmaxf(s[j][2*r], s[j][2*r+1]));
            mx = fmaxf(mx, __shfl_xor_sync(0xffffffffu, mx, 1));
            mx = fmaxf(mx, __shfl_xor_sync(0xffffffffu, mx, 2));
            float mnew  = fmaxf(mrow[r], mx);
            float alpha = fexp2(mrow[r] - mnew);
            float psum = 0.f;
            #pragma unroll
            for (int j = 0; j < 8; j++) {
                float p0 = fexp2(s[j][2*r]   - mnew);
                float p1 = fexp2(s[j][2*r+1] - mnew);
                s[j][2*r] = p0; s[j][2*r+1] = p1;
                psum += p0 + p1;
            }
            psum += __shfl_xor_sync(0xffffffffu, psum, 1);
            psum += __shfl_xor_sync(0xffffffffu, psum, 2);
            lrow[r] = lrow[r] * alpha + psum;
            mrow[r] = mnew;
            #pragma unroll
            for (int n = 0; n < 8; n++) {
                oacc[n][2*r]   *= alpha;
                oacc[n][2*r+1] *= alpha;
            }
        }

        // ---- O += P V: pack P per t-group, MMA immediately ----
        #pragma unroll
        for (int t = 0; t < 4; t++) {
            uint32_t ph[4], pl[4];
            #pragma unroll
            for (int half = 0; half < 2; half++) {
                int j = 2 * t + half;
                #pragma unroll
                for (int r = 0; r < 2; r++) {
                    float p0 = s[j][2*r], p1 = s[j][2*r+1];
                    __nv_bfloat16 h0 = __float2bfloat16_rn(p0);
                    __nv_bfloat16 h1 = __float2bfloat16_rn(p1);
                    ph[half*2 + r] = pack_bf16(p0, p1);
                    pl[half*2 + r] = pack_bf16(p0 - __bfloat162float(h0),
                                               p1 - __bfloat162float(h1));
                }
            }
            #pragma unroll
            for (int n2 = 0; n2 < 4; n2++) {
                uint32_t vh[4], vl[4];
                uint32_t va = (t * 16 + vrow) * KSTR + (n2 * 16 + vcol8) * 2;
                LDSM4T(vh, bu + 2 * TILE_B + va);
                LDSM4T(vl, bu + 3 * TILE_B + va);
                #pragma unroll
                for (int s2 = 0; s2 < 2; s2++) {
                    float* cv = oacc[n2 * 2 + s2];
                    MMA_BF16(cv, ph, vh[2*s2], vh[2*s2+1]);
                    MMA_BF16(cv, pl, vh[2*s2], vh[2*s2+1]);
                    MMA_BF16(cv, ph, vl[2*s2], vl[2*s2+1]);
                }
            }
        }
    }

    // ---- epilogue: normalize, write bf16 hi/lo ----
    #pragma unroll
    for (int r = 0; r < 2; r++) {
        float linv = 1.f / lrow[r];
        int qrow = q0 + wq + r1 + 8 * r;
        size_t base = (size_t)(b * SS + qrow) * DD + h * HD + c2;
        #pragma unroll
        for (int n = 0; n < 8; n++) {
            float p0 = oacc[n][2*r] * linv;
            float p1 = oacc[n][2*r+1] * linv;
            __nv_bfloat16 h0 = __float2bfloat16_rn(p0);
            __nv_bfloat16 h1 = __float2bfloat16_rn(p1);
            *(uint32_t*)&ohi[base + n * 8] = pack_bf16(p0, p1);
            *(uint32_t*)&olo[base + n * 8] = pack_bf16(p0 - __bfloat162float(h0),
                                                       p1 - __bfloat162float(h1));
        }
    }
}

// ---------------------------------------------------------------------------
extern "C" void kernel_launch(void* const* d_in, const int* in_sizes, int n_in,
                              void* d_out, int out_size) {
    const float* x  = (const float*)d_in[0];
    const float* Wq = (const float*)d_in[1];
    const float* Wk = (const float*)d_in[2];
    const float* Wv = (const float*)d_in[3];
    const float* Wo = (const float*)d_in[4];
    float* out = (float*)d_out;

    void *p_xhi, *p_xlo, *p_whi, *p_wlo, *p_qkvhi, *p_qkvlo, *p_ahi, *p_alo;
    cudaGetSymbolAddress(&p_xhi, g_xhi);
    cudaGetSymbolAddress(&p_xlo, g_xlo);
    cudaGetSymbolAddress(&p_whi, g_whi);
    cudaGetSymbolAddress(&p_wlo, g_wlo);
    cudaGetSymbolAddress(&p_qkvhi, g_qkvhi);
    cudaGetSymbolAddress(&p_qkvlo, g_qkvlo);
    cudaGetSymbolAddress(&p_ahi, g_ahi);
    cudaGetSymbolAddress(&p_alo, g_alo);

    __nv_bfloat16* xhi = (__nv_bfloat16*)p_xhi;
    __nv_bfloat16* xlo = (__nv_bfloat16*)p_xlo;
    __nv_bfloat16* whi = (__nv_bfloat16*)p_whi;
    __nv_bfloat16* wlo = (__nv_bfloat16*)p_wlo;
    __nv_bfloat16* qkvhi = (__nv_bfloat16*)p_qkvhi;
    __nv_bfloat16* qkvlo = (__nv_bfloat16*)p_qkvlo;
    __nv_bfloat16* ahi = (__nv_bfloat16*)p_ahi;
    __nv_bfloat16* alo = (__nv_bfloat16*)p_alo;

    const int xn4 = MTOT * DD / 4;
    const int wtot4 = 4 * DD * DD / 4;
    split_kernel<<<xn4 / 256, 256>>>(x, xhi, xlo, xn4);
    wsplit_kernel<<<(wtot4 + 255) / 256, 256>>>(Wq, Wk, Wv, Wo, whi, wlo);

    cudaFuncSetAttribute(gemm_mma<0>,
                         cudaFuncAttributeMaxDynamicSharedMemorySize, GEMM_SMEM);
    cudaFuncSetAttribute(gemm_mma<1>,
                         cudaFuncAttributeMaxDynamicSharedMemorySize, GEMM_SMEM);

    // Fused QKV projection: 768 tiles over 296 persistent CTAs
    gemm_mma<1><<<296, 256, GEMM_SMEM>>>(
        xhi, xlo, whi, wlo, nullptr, qkvhi, qkvlo,
        QKVN, QKVN / 128, (QKVN / 128) * (MTOT / 128));

    cudaFuncSetAttribute(attn_mma,
                         cudaFuncAttributeMaxDynamicSharedMemorySize, ATT_SMEM);
    attn_mma<<<dim3(SS / 64, BB * HH), 128, ATT_SMEM>>>(qkvhi, qkvlo, ahi, alo);

    // O projection: 256 tiles
    gemm_mma<0><<<256, 256, GEMM_SMEM>>>(
        ahi, alo, whi + 3*DD*DD, wlo + 3*DD*DD, out, nullptr, nullptr,
        DD, DD / 128, (DD / 128) * (MTOT / 128));
}

// round 8
// speedup vs baseline: 1.2266x; 1.2038x over previous
#include <cuda_runtime.h>
#include <math.h>
#include <stdint.h>

#define BB 2
#define SS 2048
#define DD 1024
#define HH 16
#define HD 64
#define MTOT (BB*SS)   // 4096 rows
#define QKVN 3072      // fused QKV output width

// ---------------------------------------------------------------------------
// Scratch (allocation-free rule: device globals) — fp32 holding tf32-rounded
// ---------------------------------------------------------------------------
__device__ float g_xt[MTOT*DD];          // x, tf32-rounded
__device__ float g_wt[4*DD*DD];          // Wq|Wk|Wv|Wo, tf32-rounded
__device__ float g_qkv[MTOT*QKVN];       // Q,K in [m][3072] (V third unused)
__device__ float g_vt[BB*HH*HD*SS];      // V transposed: [b][h][d][s]
__device__ float g_att[MTOT*DD];         // attention output, tf32-rounded

// ---------------------------------------------------------------------------
// PTX helpers (target-agnostic: tf32 mma.sync / ldmatrix / cp.async)
// ---------------------------------------------------------------------------
__device__ __forceinline__ uint32_t smem_u32(const void* p) {
    uint32_t a;
    asm("{ .reg .u64 t; cvta.to.shared.u64 t, %1; cvt.u32.u64 %0, t; }"
        : "=r"(a) : "l"(p));
    return a;
}
#define CP16(s, g) \
    asm volatile("cp.async.cg.shared.global [%0], [%1], 16;" \
                 :: "r"(s), "l"(g) : "memory")
#define CP_COMMIT() asm volatile("cp.async.commit_group;" ::: "memory")
#define CP_WAIT0()  asm volatile("cp.async.wait_group 0;" ::: "memory")
#define LDSM4(r, addr) \
    asm volatile("ldmatrix.sync.aligned.m8n8.x4.shared.b16 {%0,%1,%2,%3}, [%4];" \
                 : "=r"((r)[0]), "=r"((r)[1]), "=r"((r)[2]), "=r"((r)[3]) \
                 : "r"(addr))
// D = A(tf32 m16k8) * B(tf32 k8n8) + D, fp32 acc
#define MMA_TF32(c, a, b0, b1) \
    asm volatile("mma.sync.aligned.m16n8k8.row.col.f32.tf32.tf32.f32 " \
                 "{%0,%1,%2,%3}, {%4,%5,%6,%7}, {%8,%9}, {%0,%1,%2,%3};" \
                 : "+f"((c)[0]), "+f"((c)[1]), "+f"((c)[2]), "+f"((c)[3]) \
                 : "r"(__float_as_uint((a)[0])), "r"(__float_as_uint((a)[1])), \
                   "r"(__float_as_uint((a)[2])), "r"(__float_as_uint((a)[3])), \
                   "r"(__float_as_uint(b0)), "r"(__float_as_uint(b1)))
// same but A supplied as raw u32 regs (from ldmatrix)
#define MMA_TF32U(c, a, b0, b1) \
    asm volatile("mma.sync.aligned.m16n8k8.row.col.f32.tf32.tf32.f32 " \
                 "{%0,%1,%2,%3}, {%4,%5,%6,%7}, {%8,%9}, {%0,%1,%2,%3};" \
                 : "+f"((c)[0]), "+f"((c)[1]), "+f"((c)[2]), "+f"((c)[3]) \
                 : "r"((a)[0]), "r"((a)[1]), "r"((a)[2]), "r"((a)[3]), \
                   "r"((b0)), "r"((b1)))

__device__ __forceinline__ float tf32r(float x) {
    float y;
    asm("cvt.rna.tf32.f32 %0, %1;" : "=f"(y) : "f"(x));
    return y;
}
__device__ __forceinline__ float fexp2(float x) {
    float y;
    asm("ex2.approx.ftz.f32 %0, %1;" : "=f"(y) : "f"(x));
    return y;
}

// ---------------------------------------------------------------------------
// Round fp32 -> tf32 (stored as fp32)
// ---------------------------------------------------------------------------
__global__ void cvt_kernel(const float* __restrict__ in, float* __restrict__ out,
                           int n4) {
    int i = blockIdx.x * blockDim.x + threadIdx.x;
    if (i >= n4) return;
    float4 v = ((const float4*)in)[i];
    v.x = tf32r(v.x); v.y = tf32r(v.y); v.z = tf32r(v.z); v.w = tf32r(v.w);
    ((float4*)out)[i] = v;
}

__global__ void wcvt_kernel(const float* __restrict__ w0, const float* __restrict__ w1,
                            const float* __restrict__ w2, const float* __restrict__ w3,
                            float* __restrict__ out) {
    const int wn4 = DD * DD / 4;
    int idx = blockIdx.x * blockDim.x + threadIdx.x;
    if (idx >= 4 * wn4) return;
    int w = idx / wn4, i = idx - w * wn4;
    const float* src = (w == 0) ? w0 : (w == 1) ? w1 : (w == 2) ? w2 : w3;
    float4 v = ((const float4*)src)[i];
    v.x = tf32r(v.x); v.y = tf32r(v.y); v.z = tf32r(v.z); v.w = tf32r(v.w);
    ((float4*)out)[idx] = v;
}

// ---------------------------------------------------------------------------
// Persistent TF32 GEMM: C[M, Nout] = A[M,1024] * B[Nout,1024]^T
// OUTMODE 0: fp32 C (O projection).
// OUTMODE 1: QKV — Q/K tiles -> tf32-rounded into Cq (ldc=3072);
//                  V tiles (n0>=2048) -> transposed into vt [b][h][d][s].
// 128x128 tile, BK=32 fp32, 8 warps, cp.async double buffer.
// ---------------------------------------------------------------------------
#define GK 1024
#define GRS 144                  // smem row stride bytes (32 fp32 + pad)
#define GMAT (128*GRS)           // 18432 per matrix tile
#define GBUF (2*GMAT)            // 36864 per buffer (A+B)
#define GEMM_SMEM (2*GBUF)       // 73728

__device__ __forceinline__ void issue_chunk(
    const float* __restrict__ A, const float* __restrict__ B,
    int m0, int n0, int kc, uint32_t sbuf, int tid)
{
    #pragma unroll
    for (int t = 0; t < 8; t++) {
        int idx  = tid + t * 256;
        int half = idx >> 10;          // 0 = A, 1 = B
        int v    = idx & 1023;
        int row  = v >> 3;
        int c4   = v & 7;
        const float* g = half ? (B + (size_t)(n0 + row) * GK + kc + c4 * 4)
                              : (A + (size_t)(m0 + row) * GK + kc + c4 * 4);
        CP16(sbuf + half * GMAT + row * GRS + c4 * 16, g);
    }
}

template<int OUTMODE>
__global__ __launch_bounds__(256, 2)
void gemm_tf32(const float* __restrict__ A, const float* __restrict__ B,
               float* __restrict__ C, float* __restrict__ vt,
               int ldc, int ntx, int ntiles)
{
    extern __shared__ char dsm[];
    const uint32_t sb = smem_u32(dsm);

    const int tid  = threadIdx.x;
    const int lane = tid & 31;
    const int wid  = tid >> 5;
    const int wm   = (wid >> 1) * 32;
    const int wn   = (wid & 1) * 64;

    const int t4   = lane >> 3;
    const int lrow = (lane & 7) + ((t4 & 1) << 3);
    const int kbo  = (t4 >> 1) << 4;
    const int r1   = lane >> 2;
    const int cc   = (lane & 3) * 2;

    for (int tile = blockIdx.x; tile < ntiles; tile += gridDim.x) {
        const int m0 = (tile / ntx) * 128;
        const int n0 = (tile % ntx) * 128;

        float acc[2][8][4];
        #pragma unroll
        for (int mt = 0; mt < 2; mt++)
            #pragma unroll
            for (int nt = 0; nt < 8; nt++)
                #pragma unroll
                for (int i = 0; i < 4; i++) acc[mt][nt][i] = 0.f;

        issue_chunk(A, B, m0, n0, 0, sb, tid);
        CP_COMMIT();

        const int NCH = GK / 32;
        for (int c = 0; c < NCH; c++) {
            CP_WAIT0();
            __syncthreads();
            if (c + 1 < NCH) {
                issue_chunk(A, B, m0, n0, (c + 1) * 32,
                            sb + ((c + 1) & 1) * GBUF, tid);
                CP_COMMIT();
            }
            const uint32_t bu = sb + (c & 1) * GBUF;

            #pragma unroll
            for (int ks = 0; ks < 4; ks++) {        // 4 k8 steps per chunk
                const uint32_t kbyte = ks * 32 + kbo;
                uint32_t af[2][4];
                #pragma unroll
                for (int mt = 0; mt < 2; mt++)
                    LDSM4(af[mt], bu + (wm + mt * 16 + lrow) * GRS + kbyte);
                #pragma unroll
                for (int np = 0; np < 4; np++) {
                    uint32_t bf[4];
                    LDSM4(bf, bu + GMAT + (wn + np * 16 + lrow) * GRS + kbyte);
                    #pragma unroll
                    for (int mt = 0; mt < 2; mt++) {
                        MMA_TF32U(acc[mt][np * 2 + 0], af[mt], bf[0], bf[2]);
                        MMA_TF32U(acc[mt][np * 2 + 1], af[mt], bf[1], bf[3]);
                    }
                }
            }
            __syncthreads();
        }

        // ---- epilogue ----
        if (OUTMODE == 0 || n0 < 2048) {
            #pragma unroll
            for (int mt = 0; mt < 2; mt++) {
                #pragma unroll
                for (int nt = 0; nt < 8; nt++) {
                    size_t base = (size_t)(m0 + wm + mt * 16) * ldc
                                  + n0 + wn + nt * 8 + cc;
                    #pragma unroll
                    for (int r = 0; r < 2; r++) {
                        float p0 = acc[mt][nt][2*r], p1 = acc[mt][nt][2*r+1];
                        if (OUTMODE == 1) { p0 = tf32r(p0); p1 = tf32r(p1); }
                        *(float2*)&C[base + (size_t)(r1 + 8*r) * ldc] =
                            make_float2(p0, p1);
                    }
                }
            }
        } else {
            // V tiles: write transposed, tf32-rounded: vt[((b*16+h)*64+d)*2048+s]
            #pragma unroll
            for (int mt = 0; mt < 2; mt++) {
                #pragma unroll
                for (int nt = 0; nt < 8; nt++) {
                    int nb = n0 + wn + nt * 8 + cc;   // global col (>=2048)
                    #pragma unroll
                    for (int r = 0; r < 2; r++) {
                        int m = m0 + wm + mt * 16 + r1 + 8 * r;
                        int b = m >> 11, s = m & 2047;
                        #pragma unroll
                        for (int e = 0; e < 2; e++) {
                            int dg = nb + e - 2048;
                            int h = dg >> 6, d = dg & 63;
                            vt[(((size_t)b * 16 + h) * 64 + d) * 2048 + s] =
                                tf32r(acc[mt][nt][2*r + e]);
                        }
                    }
                }
            }
        }
    }
}

// ---------------------------------------------------------------------------
// TF32 flash attention — 64-row Q tiles, 128-thread CTAs.
// Q,K row-major [s][d]; V read pre-transposed [d][s]; all tf32-rounded fp32.
// ---------------------------------------------------------------------------
#define ARS 272                  // smem row stride bytes (64 fp32 + 16 pad)
#define AMAT (64*ARS)            // 17408 per tile
#define ATT_SMEM (AMAT + 2*2*AMAT)   // Q + 2 x (K,VT) = 87040
#define SM_SCALE 0.18033688011112042f  // 0.125 * log2(e)

__global__ __launch_bounds__(128, 2)
void attn_tf32(const float* __restrict__ qkv, const float* __restrict__ vtg,
               float* __restrict__ att)
{
    extern __shared__ char dsm[];
    const uint32_t sQ  = smem_u32(dsm);
    const uint32_t sKV = sQ + AMAT;     // buffer b: K at +b*2*AMAT, VT at +AMAT

    const int tid  = threadIdx.x;
    const int lane = tid & 31;
    const int wid  = tid >> 5;                 // 0..3
    const int qt   = gridDim.x - 1 - blockIdx.x;
    const int bh   = blockIdx.y;
    const int b    = bh >> 4;
    const int h    = bh & 15;
    const int q0   = qt * 64;

    const float* qbase = qkv + (size_t)b * SS * QKVN + h * HD;
    const float* kbase = qbase + DD;
    const float* vbase = vtg + ((size_t)bh * 64) * 2048;

    // ---- stage Q + first K/VT tile in one async group ----
    #pragma unroll
    for (int i = 0; i < 8; i++) {              // Q: 1024 CP16
        int idx = tid + i * 128;
        int row = idx >> 4, c4 = idx & 15;
        CP16(sQ + row * ARS + c4 * 16,
             qbase + (size_t)(q0 + row) * QKVN + c4 * 4);
    }
    #pragma unroll
    for (int i = 0; i < 16; i++) {             // K + VT: 2048 CP16
        int idx = tid + i * 128;
        int v   = idx & 1023;
        int row = v >> 4, c4 = v & 15;
        if (idx < 1024)
            CP16(sKV + row * ARS + c4 * 16,
                 kbase + (size_t)row * QKVN + c4 * 4);
        else
            CP16(sKV + AMAT + row * ARS + c4 * 16,
                 vbase + (size_t)row * 2048 + c4 * 4);
    }
    CP_COMMIT();

    const int wq   = wid * 16;
    const int t4   = lane >> 3;
    const int lrow = (lane & 7) + ((t4 & 1) << 3);
    const int kbo  = (t4 >> 1) << 4;
    const int r1   = lane >> 2;
    const int c2   = (lane & 3) * 2;
    const int sA   = (lane & ~3) | ((lane & 3) >> 1);
    const int sB   = sA + 2;
    const int par  = lane & 1;

    float oacc[8][4];
    #pragma unroll
    for (int n = 0; n < 8; n++)
        #pragma unroll
        for (int i = 0; i < 4; i++) oacc[n][i] = 0.f;
    float mrow[2] = {-INFINITY, -INFINITY};    // log2 domain
    float lrowv[2] = {0.f, 0.f};

    const int ntiles = qt + 1;
    for (int kt = 0; kt < ntiles; kt++) {
        CP_WAIT0();
        __syncthreads();
        if (kt + 1 < ntiles) {
            uint32_t nbuf = sKV + ((kt + 1) & 1) * (2 * AMAT);
            #pragma unroll
            for (int i = 0; i < 16; i++) {
                int idx = tid + i * 128;
                int v   = idx & 1023;
                int row = v >> 4, c4 = v & 15;
                if (idx < 1024)
                    CP16(nbuf + row * ARS + c4 * 16,
                         kbase + (size_t)((kt + 1) * 64 + row) * QKVN + c4 * 4);
                else
                    CP16(nbuf + AMAT + row * ARS + c4 * 16,
                         vbase + (size_t)row * 2048 + (kt + 1) * 64 + c4 * 4);
            }
            CP_COMMIT();
        }
        const uint32_t buK = sKV + (kt & 1) * (2 * AMAT);
        const uint32_t buV = buK + AMAT;

        // ---- S = Q K^T (single tf32 pass) ----
        float s[8][4];
        #pragma unroll
        for (int j = 0; j < 8; j++)
            #pragma unroll
            for (int i = 0; i < 4; i++) s[j][i] = 0.f;

        #pragma unroll
        for (int kg = 0; kg < 8; kg++) {
            const uint32_t kbyte = kg * 32 + kbo;
            uint32_t qf[4];
            LDSM4(qf, sQ + (wq + lrow) * ARS + kbyte);
            #pragma unroll
            for (int j2 = 0; j2 < 4; j2++) {
                uint32_t kf[4];
                LDSM4(kf, buK + (j2 * 16 + lrow) * ARS + kbyte);
                MMA_TF32U(s[j2 * 2 + 0], qf, kf[0], kf[2]);
                MMA_TF32U(s[j2 * 2 + 1], qf, kf[1], kf[3]);
            }
        }

        // ---- scale (exp2 domain) + causal mask (diagonal tile only) ----
        const bool masked = (kt == ntiles - 1);
        #pragma unroll
        for (int j = 0; j < 8; j++) {
            #pragma unroll
            for (int i = 0; i < 4; i++) {
                float sv = s[j][i] * SM_SCALE;
                if (masked) {
                    int qrow = wq + r1 + ((i >> 1) << 3);
                    int key  = j * 8 + c2 + (i & 1);
                    if (key > qrow) sv = -INFINITY;
                }
                s[j][i] = sv;
            }
        }

        // ---- online softmax (exp2 domain) ----
        #pragma unroll
        for (int r = 0; r < 2; r++) {
            float mx = -INFINITY;
            #pragma unroll
            for (int j = 0; j < 8; j++)
                mx = fmaxf(mx, fmaxf(s[j][2*r], s[j][2*r+1]));
            mx = fmaxf(mx, __shfl_xor_sync(0xffffffffu, mx, 1));
            mx = fmaxf(mx, __shfl_xor_sync(0xffffffffu, mx, 2));
            float mnew  = fmaxf(mrow[r], mx);
            float alpha = fexp2(mrow[r] - mnew);
            float psum = 0.f;
            #pragma unroll
            for (int j = 0; j < 8; j++) {
                float p0 = fexp2(s[j][2*r]   - mnew);
                float p1 = fexp2(s[j][2*r+1] - mnew);
                s[j][2*r] = p0; s[j][2*r+1] = p1;
                psum += p0 + p1;
            }
            psum += __shfl_xor_sync(0xffffffffu, psum, 1);
            psum += __shfl_xor_sync(0xffffffffu, psum, 2);
            lrowv[r] = lrowv[r] * alpha + psum;
            mrow[r] = mnew;
            #pragma unroll
            for (int n = 0; n < 8; n++) {
                oacc[n][2*r]   *= alpha;
                oacc[n][2*r+1] *= alpha;
            }
        }

        // ---- O += P V : rearrange S-frag -> tf32 A-frag via shfl, B from VT ----
        #pragma unroll
        for (int kg = 0; kg < 8; kg++) {
            float pa[4];
            {
                float e0 = __shfl_sync(0xffffffffu, s[kg][0], sA);
                float e1 = __shfl_sync(0xffffffffu, s[kg][1], sA);
                float e2 = __shfl_sync(0xffffffffu, s[kg][2], sA);
                float e3 = __shfl_sync(0xffffffffu, s[kg][3], sA);
                float f0 = __shfl_sync(0xffffffffu, s[kg][0], sB);
                float f1 = __shfl_sync(0xffffffffu, s[kg][1], sB);
                float f2 = __shfl_sync(0xffffffffu, s[kg][2], sB);
                float f3 = __shfl_sync(0xffffffffu, s[kg][3], sB);
                pa[0] = tf32r(par ? e1 : e0);   // P(r1,   c)
                pa[1] = tf32r(par ? e3 : e2);   // P(r1+8, c)
                pa[2] = tf32r(par ? f1 : f0);   // P(r1,   c+4)
                pa[3] = tf32r(par ? f3 : f2);   // P(r1+8, c+4)
            }
            const uint32_t kbyte = kg * 32 + kbo;
            #pragma unroll
            for (int n2 = 0; n2 < 4; n2++) {
                uint32_t vf[4];
                LDSM4(vf, buV + (n2 * 16 + lrow) * ARS + kbyte);
                MMA_TF32(oacc[n2 * 2 + 0], pa, __uint_as_float(vf[0]),
                                               __uint_as_float(vf[2]));
                MMA_TF32(oacc[n2 * 2 + 1], pa, __uint_as_float(vf[1]),
                                               __uint_as_float(vf[3]));
            }
        }
    }

    // ---- epilogue: normalize, tf32-round, store fp32 ----
    #pragma unroll
    for (int r = 0; r < 2; r++) {
        float linv = 1.f / lrowv[r];
        int qrow = q0 + wq + r1 + 8 * r;
        size_t base = (size_t)(b * SS + qrow) * DD + h * HD + c2;
        #pragma unroll
        for (int n = 0; n < 8; n++) {
            float p0 = tf32r(oacc[n][2*r] * linv);
            float p1 = tf32r(oacc[n][2*r+1] * linv);
            *(float2*)&att[base + n * 8] = make_float2(p0, p1);
        }
    }
}

// ---------------------------------------------------------------------------
extern "C" void kernel_launch(void* const* d_in, const int* in_sizes, int n_in,
                              void* d_out, int out_size) {
    const float* x  = (const float*)d_in[0];
    const float* Wq = (const float*)d_in[1];
    const float* Wk = (const float*)d_in[2];
    const float* Wv = (const float*)d_in[3];
    const float* Wo = (const float*)d_in[4];
    float* out = (float*)d_out;

    void *p_xt, *p_wt, *p_qkv, *p_vt, *p_att;
    cudaGetSymbolAddress(&p_xt, g_xt);
    cudaGetSymbolAddress(&p_wt, g_wt);
    cudaGetSymbolAddress(&p_qkv, g_qkv);
    cudaGetSymbolAddress(&p_vt, g_vt);
    cudaGetSymbolAddress(&p_att, g_att);

    float* xt  = (float*)p_xt;
    float* wt  = (float*)p_wt;
    float* qkv = (float*)p_qkv;
    float* vt  = (float*)p_vt;
    float* att = (float*)p_att;

    const int xn4 = MTOT * DD / 4;
    const int wtot4 = 4 * DD * DD / 4;
    cvt_kernel<<<xn4 / 256, 256>>>(x, xt, xn4);
    wcvt_kernel<<<(wtot4 + 255) / 256, 256>>>(Wq, Wk, Wv, Wo, wt);

    cudaFuncSetAttribute(gemm_tf32<0>,
                         cudaFuncAttributeMaxDynamicSharedMemorySize, GEMM_SMEM);
    cudaFuncSetAttribute(gemm_tf32<1>,
                         cudaFuncAttributeMaxDynamicSharedMemorySize, GEMM_SMEM);

    // Fused QKV projection: 768 tiles (24 x 32) over persistent CTAs
    gemm_tf32<1><<<304, 256, GEMM_SMEM>>>(
        xt, wt, qkv, vt, QKVN, QKVN / 128, (QKVN / 128) * (MTOT / 128));

    cudaFuncSetAttribute(attn_tf32,
                         cudaFuncAttributeMaxDynamicSharedMemorySize, ATT_SMEM);
    attn_tf32<<<dim3(SS / 64, BB * HH), 128, ATT_SMEM>>>(qkv, vt, att);

    // O projection: 256 tiles (8 x 32)
    gemm_tf32<0><<<256, 256, GEMM_SMEM>>>(
        att, wt + 3*DD*DD, out, nullptr, DD, DD / 128, (DD / 128) * (MTOT / 128));
}

// round 9
// speedup vs baseline: 1.2327x; 1.0050x over previous
#include <cuda_runtime.h>
#include <math.h>
#include <stdint.h>

#define BB 2
#define SS 2048
#define DD 1024
#define HH 16
#define HD 64
#define MTOT (BB*SS)   // 4096 rows
#define QKVN 3072      // fused QKV output width

// ---------------------------------------------------------------------------
// Scratch (allocation-free rule: device globals) — fp32 holding tf32-rounded
// ---------------------------------------------------------------------------
__device__ float g_xt[MTOT*DD];          // x, tf32-rounded
__device__ float g_wt[4*DD*DD];          // Wq|Wk|Wv|Wo, tf32-rounded
__device__ float g_qkv[MTOT*QKVN];       // Q,K in [m][3072] (V third unused)
__device__ float g_vt[BB*HH*HD*SS];      // V transposed: [b][h][d][s]
__device__ float g_att[MTOT*DD];         // attention output, tf32-rounded

// ---------------------------------------------------------------------------
// PTX helpers (target-agnostic: tf32 mma.sync / ldmatrix / cp.async)
// ---------------------------------------------------------------------------
__device__ __forceinline__ uint32_t smem_u32(const void* p) {
    uint32_t a;
    asm("{ .reg .u64 t; cvta.to.shared.u64 t, %1; cvt.u32.u64 %0, t; }"
        : "=r"(a) : "l"(p));
    return a;
}
#define CP16(s, g) \
    asm volatile("cp.async.cg.shared.global [%0], [%1], 16;" \
                 :: "r"(s), "l"(g) : "memory")
#define CP_COMMIT() asm volatile("cp.async.commit_group;" ::: "memory")
#define CP_WAIT0()  asm volatile("cp.async.wait_group 0;" ::: "memory")
#define LDSM4(r, addr) \
    asm volatile("ldmatrix.sync.aligned.m8n8.x4.shared.b16 {%0,%1,%2,%3}, [%4];" \
                 : "=r"((r)[0]), "=r"((r)[1]), "=r"((r)[2]), "=r"((r)[3]) \
                 : "r"(addr))
#define MMA_TF32(c, a, b0, b1) \
    asm volatile("mma.sync.aligned.m16n8k8.row.col.f32.tf32.tf32.f32 " \
                 "{%0,%1,%2,%3}, {%4,%5,%6,%7}, {%8,%9}, {%0,%1,%2,%3};" \
                 : "+f"((c)[0]), "+f"((c)[1]), "+f"((c)[2]), "+f"((c)[3]) \
                 : "r"(__float_as_uint((a)[0])), "r"(__float_as_uint((a)[1])), \
                   "r"(__float_as_uint((a)[2])), "r"(__float_as_uint((a)[3])), \
                   "r"(__float_as_uint(b0)), "r"(__float_as_uint(b1)))
#define MMA_TF32U(c, a, b0, b1) \
    asm volatile("mma.sync.aligned.m16n8k8.row.col.f32.tf32.tf32.f32 " \
                 "{%0,%1,%2,%3}, {%4,%5,%6,%7}, {%8,%9}, {%0,%1,%2,%3};" \
                 : "+f"((c)[0]), "+f"((c)[1]), "+f"((c)[2]), "+f"((c)[3]) \
                 : "r"((a)[0]), "r"((a)[1]), "r"((a)[2]), "r"((a)[3]), \
                   "r"((b0)), "r"((b1)))

__device__ __forceinline__ float tf32r(float x) {
    float y;
    asm("cvt.rna.tf32.f32 %0, %1;" : "=f"(y) : "f"(x));
    return y;
}
__device__ __forceinline__ float fexp2(float x) {
    float y;
    asm("ex2.approx.ftz.f32 %0, %1;" : "=f"(y) : "f"(x));
    return y;
}

// ---------------------------------------------------------------------------
// Round fp32 -> tf32 (stored as fp32)
// ---------------------------------------------------------------------------
__global__ void cvt_kernel(const float* __restrict__ in, float* __restrict__ out,
                           int n4) {
    int i = blockIdx.x * blockDim.x + threadIdx.x;
    if (i >= n4) return;
    float4 v = ((const float4*)in)[i];
    v.x = tf32r(v.x); v.y = tf32r(v.y); v.z = tf32r(v.z); v.w = tf32r(v.w);
    ((float4*)out)[i] = v;
}

__global__ void wcvt_kernel(const float* __restrict__ w0, const float* __restrict__ w1,
                            const float* __restrict__ w2, const float* __restrict__ w3,
                            float* __restrict__ out) {
    const int wn4 = DD * DD / 4;
    int idx = blockIdx.x * blockDim.x + threadIdx.x;
    if (idx >= 4 * wn4) return;
    int w = idx / wn4, i = idx - w * wn4;
    const float* src = (w == 0) ? w0 : (w == 1) ? w1 : (w == 2) ? w2 : w3;
    float4 v = ((const float4*)src)[i];
    v.x = tf32r(v.x); v.y = tf32r(v.y); v.z = tf32r(v.z); v.w = tf32r(v.w);
    ((float4*)out)[idx] = v;
}

// ---------------------------------------------------------------------------
// Persistent TF32 GEMM: C[M, Nout] = A[M,1024] * B[Nout,1024]^T
// 256x128 CTA tile (8 warps as 4x2, warp tile 64x64), BK=32, double buffer.
// OUTMODE 0: fp32 C.  OUTMODE 1: QKV with V tiles (n0>=2048) transposed.
// ---------------------------------------------------------------------------
#define GK 1024
#define GRS 144                  // smem row stride bytes (32 fp32 + 16 pad)
#define GMS_A (256*GRS)          // 36864
#define GMS_B (128*GRS)          // 18432
#define GBUF (GMS_A + GMS_B)     // 55296 per buffer
#define GEMM_SMEM (2*GBUF)       // 110592

__device__ __forceinline__ void issue_chunk(
    const float* __restrict__ A, const float* __restrict__ B,
    int m0, int n0, int kc, uint32_t sbuf, int tid)
{
    #pragma unroll
    for (int t = 0; t < 12; t++) {       // 3072 CP16: A 2048, B 1024
        int idx = tid + t * 256;
        if (idx < 2048) {
            int row = idx >> 3, c4 = idx & 7;
            CP16(sbuf + row * GRS + c4 * 16,
                 A + (size_t)(m0 + row) * GK + kc + c4 * 4);
        } else {
            int v = idx - 2048;
            int row = v >> 3, c4 = v & 7;
            CP16(sbuf + GMS_A + row * GRS + c4 * 16,
                 B + (size_t)(n0 + row) * GK + kc + c4 * 4);
        }
    }
}

template<int OUTMODE>
__global__ __launch_bounds__(256, 1)
void gemm_tf32(const float* __restrict__ A, const float* __restrict__ B,
               float* __restrict__ C, float* __restrict__ vt,
               int ldc, int ntx, int ntiles)
{
    extern __shared__ char dsm[];
    const uint32_t sb = smem_u32(dsm);

    const int tid  = threadIdx.x;
    const int lane = tid & 31;
    const int wid  = tid >> 5;
    const int wm   = (wid >> 1) * 64;    // 4 warp-groups in M
    const int wn   = (wid & 1) * 64;     // 2 in N

    const int t4   = lane >> 3;
    const int lrow = (lane & 7) + ((t4 & 1) << 3);
    const int kbo  = (t4 >> 1) << 4;
    const int r1   = lane >> 2;
    const int cc   = (lane & 3) * 2;

    for (int tile = blockIdx.x; tile < ntiles; tile += gridDim.x) {
        const int m0 = (tile / ntx) * 256;
        const int n0 = (tile % ntx) * 128;

        float acc[4][8][4];
        #pragma unroll
        for (int mt = 0; mt < 4; mt++)
            #pragma unroll
            for (int nt = 0; nt < 8; nt++)
                #pragma unroll
                for (int i = 0; i < 4; i++) acc[mt][nt][i] = 0.f;

        issue_chunk(A, B, m0, n0, 0, sb, tid);
        CP_COMMIT();

        const int NCH = GK / 32;
        for (int c = 0; c < NCH; c++) {
            CP_WAIT0();
            __syncthreads();
            if (c + 1 < NCH) {
                issue_chunk(A, B, m0, n0, (c + 1) * 32,
                            sb + ((c + 1) & 1) * GBUF, tid);
                CP_COMMIT();
            }
            const uint32_t bu = sb + (c & 1) * GBUF;

            #pragma unroll
            for (int ks = 0; ks < 4; ks++) {        // 4 k8 steps per chunk
                const uint32_t kbyte = ks * 32 + kbo;
                uint32_t af[4][4];
                #pragma unroll
                for (int mt = 0; mt < 4; mt++)
                    LDSM4(af[mt], bu + (wm + mt * 16 + lrow) * GRS + kbyte);
                #pragma unroll
                for (int np = 0; np < 4; np++) {
                    uint32_t bf[4];
                    LDSM4(bf, bu + GMS_A + (wn + np * 16 + lrow) * GRS + kbyte);
                    #pragma unroll
                    for (int mt = 0; mt < 4; mt++) {
                        MMA_TF32U(acc[mt][np * 2 + 0], af[mt], bf[0], bf[2]);
                        MMA_TF32U(acc[mt][np * 2 + 1], af[mt], bf[1], bf[3]);
                    }
                }
            }
            __syncthreads();
        }

        // ---- epilogue ----
        if (OUTMODE == 0 || n0 < 2048) {
            #pragma unroll
            for (int mt = 0; mt < 4; mt++) {
                #pragma unroll
                for (int nt = 0; nt < 8; nt++) {
                    size_t base = (size_t)(m0 + wm + mt * 16) * ldc
                                  + n0 + wn + nt * 8 + cc;
                    #pragma unroll
                    for (int r = 0; r < 2; r++) {
                        float p0 = acc[mt][nt][2*r], p1 = acc[mt][nt][2*r+1];
                        if (OUTMODE == 1) { p0 = tf32r(p0); p1 = tf32r(p1); }
                        *(float2*)&C[base + (size_t)(r1 + 8*r) * ldc] =
                            make_float2(p0, p1);
                    }
                }
            }
        } else {
            // V tiles: write transposed, tf32-rounded: vt[((b*16+h)*64+d)*2048+s]
            #pragma unroll
            for (int mt = 0; mt < 4; mt++) {
                #pragma unroll
                for (int nt = 0; nt < 8; nt++) {
                    int nb = n0 + wn + nt * 8 + cc;   // global col (>=2048)
                    #pragma unroll
                    for (int r = 0; r < 2; r++) {
                        int m = m0 + wm + mt * 16 + r1 + 8 * r;
                        int b = m >> 11, s = m & 2047;
                        #pragma unroll
                        for (int e = 0; e < 2; e++) {
                            int dg = nb + e - 2048;
                            int h = dg >> 6, d = dg & 63;
                            vt[(((size_t)b * 16 + h) * 64 + d) * 2048 + s] =
                                tf32r(acc[mt][nt][2*r + e]);
                        }
                    }
                }
            }
        }
    }
}

// ---------------------------------------------------------------------------
// TF32 flash attention — 64-row Q tiles, 128-thread CTAs (unchanged from R8).
// ---------------------------------------------------------------------------
#define ARS 272                  // smem row stride bytes (64 fp32 + 16 pad)
#define AMAT (64*ARS)            // 17408 per tile
#define ATT_SMEM (AMAT + 2*2*AMAT)   // Q + 2 x (K,VT) = 87040
#define SM_SCALE 0.18033688011112042f  // 0.125 * log2(e)

__global__ __launch_bounds__(128, 2)
void attn_tf32(const float* __restrict__ qkv, const float* __restrict__ vtg,
               float* __restrict__ att)
{
    extern __shared__ char dsm[];
    const uint32_t sQ  = smem_u32(dsm);
    const uint32_t sKV = sQ + AMAT;

    const int tid  = threadIdx.x;
    const int lane = tid & 31;
    const int wid  = tid >> 5;
    const int qt   = gridDim.x - 1 - blockIdx.x;
    const int bh   = blockIdx.y;
    const int b    = bh >> 4;
    const int h    = bh & 15;
    const int q0   = qt * 64;

    const float* qbase = qkv + (size_t)b * SS * QKVN + h * HD;
    const float* kbase = qbase + DD;
    const float* vbase = vtg + ((size_t)bh * 64) * 2048;

    #pragma unroll
    for (int i = 0; i < 8; i++) {              // Q: 1024 CP16
        int idx = tid + i * 128;
        int row = idx >> 4, c4 = idx & 15;
        CP16(sQ + row * ARS + c4 * 16,
             qbase + (size_t)(q0 + row) * QKVN + c4 * 4);
    }
    #pragma unroll
    for (int i = 0; i < 16; i++) {             // K + VT: 2048 CP16
        int idx = tid + i * 128;
        int v   = idx & 1023;
        int row = v >> 4, c4 = v & 15;
        if (idx < 1024)
            CP16(sKV + row * ARS + c4 * 16,
                 kbase + (size_t)row * QKVN + c4 * 4);
        else
            CP16(sKV + AMAT + row * ARS + c4 * 16,
                 vbase + (size_t)row * 2048 + c4 * 4);
    }
    CP_COMMIT();

    const int wq   = wid * 16;
    const int t4   = lane >> 3;
    const int lrow = (lane & 7) + ((t4 & 1) << 3);
    const int kbo  = (t4 >> 1) << 4;
    const int r1   = lane >> 2;
    const int c2   = (lane & 3) * 2;
    const int sA   = (lane & ~3) | ((lane & 3) >> 1);
    const int sB   = sA + 2;
    const int par  = lane & 1;

    float oacc[8][4];
    #pragma unroll
    for (int n = 0; n < 8; n++)
        #pragma unroll
        for (int i = 0; i < 4; i++) oacc[n][i] = 0.f;
    float mrow[2] = {-INFINITY, -INFINITY};
    float lrowv[2] = {0.f, 0.f};

    const int ntiles = qt + 1;
    for (int kt = 0; kt < ntiles; kt++) {
        CP_WAIT0();
        __syncthreads();
        if (kt + 1 < ntiles) {
            uint32_t nbuf = sKV + ((kt + 1) & 1) * (2 * AMAT);
            #pragma unroll
            for (int i = 0; i < 16; i++) {
                int idx = tid + i * 128;
                int v   = idx & 1023;
                int row = v >> 4, c4 = v & 15;
                if (idx < 1024)
                    CP16(nbuf + row * ARS + c4 * 16,
                         kbase + (size_t)((kt + 1) * 64 + row) * QKVN + c4 * 4);
                else
                    CP16(nbuf + AMAT + row * ARS + c4 * 16,
                         vbase + (size_t)row * 2048 + (kt + 1) * 64 + c4 * 4);
            }
            CP_COMMIT();
        }
        const uint32_t buK = sKV + (kt & 1) * (2 * AMAT);
        const uint32_t buV = buK + AMAT;

        float s[8][4];
        #pragma unroll
        for (int j = 0; j < 8; j++)
            #pragma unroll
            for (int i = 0; i < 4; i++) s[j][i] = 0.f;

        #pragma unroll
        for (int kg = 0; kg < 8; kg++) {
            const uint32_t kbyte = kg * 32 + kbo;
            uint32_t qf[4];
            LDSM4(qf, sQ + (wq + lrow) * ARS + kbyte);
            #pragma unroll
            for (int j2 = 0; j2 < 4; j2++) {
                uint32_t kf[4];
                LDSM4(kf, buK + (j2 * 16 + lrow) * ARS + kbyte);
                MMA_TF32U(s[j2 * 2 + 0], qf, kf[0], kf[2]);
                MMA_TF32U(s[j2 * 2 + 1], qf, kf[1], kf[3]);
            }
        }

        const bool masked = (kt == ntiles - 1);
        #pragma unroll
        for (int j = 0; j < 8; j++) {
            #pragma unroll
            for (int i = 0; i < 4; i++) {
                float sv = s[j][i] * SM_SCALE;
                if (masked) {
                    int qrow = wq + r1 + ((i >> 1) << 3);
                    int key  = j * 8 + c2 + (i & 1);
                    if (key > qrow) sv = -INFINITY;
                }
                s[j][i] = sv;
            }
        }

        #pragma unroll
        for (int r = 0; r < 2; r++) {
            float mx = -INFINITY;
            #pragma unroll
            for (int j = 0; j < 8; j++)
                mx = fmaxf(mx, fmaxf(s[j][2*r], s[j][2*r+1]));
            mx = fmaxf(mx, __shfl_xor_sync(0xffffffffu, mx, 1));
            mx = fmaxf(mx, __shfl_xor_sync(0xffffffffu, mx, 2));
            float mnew  = fmaxf(mrow[r], mx);
            float alpha = fexp2(mrow[r] - mnew);
            float psum = 0.f;
            #pragma unroll
            for (int j = 0; j < 8; j++) {
                float p0 = fexp2(s[j][2*r]   - mnew);
                float p1 = fexp2(s[j][2*r+1] - mnew);
                s[j][2*r] = p0; s[j][2*r+1] = p1;
                psum += p0 + p1;
            }
            psum += __shfl_xor_sync(0xffffffffu, psum, 1);
            psum += __shfl_xor_sync(0xffffffffu, psum, 2);
            lrowv[r] = lrowv[r] * alpha + psum;
            mrow[r] = mnew;
            #pragma unroll
            for (int n = 0; n < 8; n++) {
                oacc[n][2*r]   *= alpha;
                oacc[n][2*r+1] *= alpha;
            }
        }

        #pragma unroll
        for (int kg = 0; kg < 8; kg++) {
            float pa[4];
            {
                float e0 = __shfl_sync(0xffffffffu, s[kg][0], sA);
                float e1 = __shfl_sync(0xffffffffu, s[kg][1], sA);
                float e2 = __shfl_sync(0xffffffffu, s[kg][2], sA);
                float e3 = __shfl_sync(0xffffffffu, s[kg][3], sA);
                float f0 = __shfl_sync(0xffffffffu, s[kg][0], sB);
                float f1 = __shfl_sync(0xffffffffu, s[kg][1], sB);
                float f2 = __shfl_sync(0xffffffffu, s[kg][2], sB);
                float f3 = __shfl_sync(0xffffffffu, s[kg][3], sB);
                pa[0] = tf32r(par ? e1 : e0);
                pa[1] = tf32r(par ? e3 : e2);
                pa[2] = tf32r(par ? f1 : f0);
                pa[3] = tf32r(par ? f3 : f2);
            }
            const uint32_t kbyte = kg * 32 + kbo;
            #pragma unroll
            for (int n2 = 0; n2 < 4; n2++) {
                uint32_t vf[4];
                LDSM4(vf, buV + (n2 * 16 + lrow) * ARS + kbyte);
                MMA_TF32(oacc[n2 * 2 + 0], pa, __uint_as_float(vf[0]),
                                               __uint_as_float(vf[2]));
                MMA_TF32(oacc[n2 * 2 + 1], pa, __uint_as_float(vf[1]),
                                               __uint_as_float(vf[3]));
            }
        }
    }

    #pragma unroll
    for (int r = 0; r < 2; r++) {
        float linv = 1.f / lrowv[r];
        int qrow = q0 + wq + r1 + 8 * r;
        size_t base = (size_t)(b * SS + qrow) * DD + h * HD + c2;
        #pragma unroll
        for (int n = 0; n < 8; n++) {
            float p0 = tf32r(oacc[n][2*r] * linv);
            float p1 = tf32r(oacc[n][2*r+1] * linv);
            *(float2*)&att[base + n * 8] = make_float2(p0, p1);
        }
    }
}

// ---------------------------------------------------------------------------
extern "C" void kernel_launch(void* const* d_in, const int* in_sizes, int n_in,
                              void* d_out, int out_size) {
    const float* x  = (const float*)d_in[0];
    const float* Wq = (const float*)d_in[1];
    const float* Wk = (const float*)d_in[2];
    const float* Wv = (const float*)d_in[3];
    const float* Wo = (const float*)d_in[4];
    float* out = (float*)d_out;

    void *p_xt, *p_wt, *p_qkv, *p_vt, *p_att;
    cudaGetSymbolAddress(&p_xt, g_xt);
    cudaGetSymbolAddress(&p_wt, g_wt);
    cudaGetSymbolAddress(&p_qkv, g_qkv);
    cudaGetSymbolAddress(&p_vt, g_vt);
    cudaGetSymbolAddress(&p_att, g_att);

    float* xt  = (float*)p_xt;
    float* wt  = (float*)p_wt;
    float* qkv = (float*)p_qkv;
    float* vt  = (float*)p_vt;
    float* att = (float*)p_att;

    const int xn4 = MTOT * DD / 4;
    const int wtot4 = 4 * DD * DD / 4;
    cvt_kernel<<<xn4 / 256, 256>>>(x, xt, xn4);
    wcvt_kernel<<<(wtot4 + 255) / 256, 256>>>(Wq, Wk, Wv, Wo, wt);

    cudaFuncSetAttribute(gemm_tf32<0>,
                         cudaFuncAttributeMaxDynamicSharedMemorySize, GEMM_SMEM);
    cudaFuncSetAttribute(gemm_tf32<1>,
                         cudaFuncAttributeMaxDynamicSharedMemorySize, GEMM_SMEM);

    // Fused QKV projection: 384 tiles (16m x 24n) over 148 persistent CTAs
    gemm_tf32<1><<<148, 256, GEMM_SMEM>>>(
        xt, wt, qkv, vt, QKVN, QKVN / 128, (MTOT / 256) * (QKVN / 128));

    cudaFuncSetAttribute(attn_tf32,
                         cudaFuncAttributeMaxDynamicSharedMemorySize, ATT_SMEM);
    attn_tf32<<<dim3(SS / 64, BB * HH), 128, ATT_SMEM>>>(qkv, vt, att);

    // O projection: 128 tiles (16m x 8n), one wave
    gemm_tf32<0><<<128, 256, GEMM_SMEM>>>(
        att, wt + 3*DD*DD, out, nullptr, DD, DD / 128, (MTOT / 256) * (DD / 128));
}